// round 6
// baseline (speedup 1.0000x reference)
#include <cuda_runtime.h>
#include <cstdint>

#define B_ 128
#define T_ 64
#define D_ 256
#define H_ 256
#define NT 512
#define QFLOATS 16384            // 64 k-rows x 256 cols per quarter
#define QBYTES  65536
#define NSLOT 3
#define NQ_TOTAL (T_ * 2 * 16)   // 2048 quarters total per CTA

// 64 persistent CTAs x 512 threads; each CTA owns 2 batch rows, full columns.
// Weights stream through a 3-slot x 64KB smem ring filled by cp.async.bulk
// (one elected thread per phase, rotating across warps) with full/empty
// mbarriers; compute never touches gmem for weights. Thread (q=tid&63 -> 4
// output cols, kc=tid>>6 -> k-sub of 8 rows per 64-row phase) accumulates
// float4 partials for both batch rows; 128 reducer threads fold 8 partials,
// apply bias (cp.async-prefetched into smem) + activation.

struct WPtrs { const float *Win0, *Wh0, *Win1, *Wh1; };

__device__ __forceinline__ uint32_t smem_u32(const void* p) {
    return (uint32_t)__cvta_generic_to_shared(p);
}
__device__ __forceinline__ void mbar_init_(uint32_t a, uint32_t n) {
    asm volatile("mbarrier.init.shared.b64 [%0], %1;" :: "r"(a), "r"(n) : "memory");
}
__device__ __forceinline__ void mbar_arrive_(uint32_t a) {
    asm volatile("mbarrier.arrive.shared.b64 _, [%0];" :: "r"(a) : "memory");
}
__device__ __forceinline__ void mbar_expect_tx_(uint32_t a, uint32_t tx) {
    asm volatile("mbarrier.arrive.expect_tx.shared.b64 _, [%0], %1;"
                 :: "r"(a), "r"(tx) : "memory");
}
__device__ __forceinline__ void mbar_wait_(uint32_t a, uint32_t par) {
    uint32_t done;
    asm volatile("{\n\t.reg .pred p;\n\t"
        "mbarrier.try_wait.parity.acquire.cta.shared::cta.b64 p, [%1], %2;\n\t"
        "selp.b32 %0, 1, 0, p;\n\t}"
        : "=r"(done) : "r"(a), "r"(par) : "memory");
    if (!done) {
        asm volatile("{\n\t.reg .pred P1;\n\t"
            "WL%=:\n\t"
            "mbarrier.try_wait.parity.acquire.cta.shared::cta.b64 P1, [%0], %1, 0x989680;\n\t"
            "@P1 bra WD%=;\n\t"
            "bra WL%=;\n\t"
            "WD%=:\n\t}" :: "r"(a), "r"(par) : "memory");
    }
}
__device__ __forceinline__ void bulk_g2s_(uint32_t dst, const void* src,
                                          uint32_t bytes, uint32_t mbar) {
    asm volatile("cp.async.bulk.shared::cluster.global.mbarrier::complete_tx::bytes "
                 "[%0], [%1], %2, [%3];"
                 :: "r"(dst), "l"(src), "r"(bytes), "r"(mbar) : "memory");
}
__device__ __forceinline__ void cpasync16_(uint32_t dst, const void* src) {
    asm volatile("cp.async.ca.shared.global [%0], [%1], 16;"
                 :: "r"(dst), "l"(src) : "memory");
}
__device__ __forceinline__ void cpasync_commit_() {
    asm volatile("cp.async.commit_group;" ::: "memory");
}
__device__ __forceinline__ void cpasync_wait0_() {
    asm volatile("cp.async.wait_group 0;" ::: "memory");
}

__device__ __forceinline__ void f4fma(float4& a, float s, const float4 w) {
    a.x = fmaf(s, w.x, a.x); a.y = fmaf(s, w.y, a.y);
    a.z = fmaf(s, w.z, a.z); a.w = fmaf(s, w.w, a.w);
}
__device__ __forceinline__ float4 f4add(float4 a, float4 b) {
    return make_float4(a.x + b.x, a.y + b.y, a.z + b.z, a.w + b.w);
}

// global quarter index -> gmem address
__device__ __forceinline__ const float* quarter_addr(const WPtrs& w, int g) {
    int cell = g >> 4;            // 0..127
    int within = g & 15;
    int t = cell >> 1;
    int layer = cell & 1;
    int qi = within & 3;          // quarter within matrix
    int mat = within >> 2;        // 0: Wi, 1..3: Wh[mat-1]
    const float* base;
    if (mat == 0)
        base = (layer ? w.Win1 : w.Win0) + (size_t)t * (D_ * H_);
    else
        base = (layer ? w.Wh1 : w.Wh0) + (size_t)t * (3 * H_ * H_)
               + (size_t)(mat - 1) * (H_ * H_);
    return base + (size_t)qi * QFLOATS;
}

extern __shared__ float ring[];   // NSLOT * QFLOATS

// consume quarter g (phase p of its matrix) against activations act[2][256]
__device__ __forceinline__ void consume_phase(
    int g, int p, const float (*act)[H_],
    float4& acc0, float4& acc1,
    uint64_t* fullb, uint64_t* emptyb,
    const WPtrs& wp, int tid, int q, int kc)
{
    const int s = g % NSLOT;
    const uint32_t fb = smem_u32(&fullb[s]);
    const uint32_t eb = smem_u32(&emptyb[s]);
    mbar_wait_(fb, (uint32_t)((g / NSLOT) & 1));

    const float* ws = ring + s * QFLOATS;
    const float4* w4 = reinterpret_cast<const float4*>(ws) + (kc * 8) * (H_ / 4) + q;
    const float4* a0 = reinterpret_cast<const float4*>(act[0]) + (p * 16 + kc * 2);
    const float4* a1 = reinterpret_cast<const float4*>(act[1]) + (p * 16 + kc * 2);

    float4 w0 = w4[0 * 64], w1 = w4[1 * 64], w2 = w4[2 * 64], w3 = w4[3 * 64];
    float4 w4r = w4[4 * 64], w5 = w4[5 * 64], w6 = w4[6 * 64], w7 = w4[7 * 64];
    float4 A0a = a0[0], A0b = a0[1], A1a = a1[0], A1b = a1[1];

    f4fma(acc0, A0a.x, w0);  f4fma(acc1, A1a.x, w0);
    f4fma(acc0, A0a.y, w1);  f4fma(acc1, A1a.y, w1);
    f4fma(acc0, A0a.z, w2);  f4fma(acc1, A1a.z, w2);
    f4fma(acc0, A0a.w, w3);  f4fma(acc1, A1a.w, w3);
    f4fma(acc0, A0b.x, w4r); f4fma(acc1, A1b.x, w4r);
    f4fma(acc0, A0b.y, w5);  f4fma(acc1, A1b.y, w5);
    f4fma(acc0, A0b.z, w6);  f4fma(acc1, A1b.z, w6);
    f4fma(acc0, A0b.w, w7);  f4fma(acc1, A1b.w, w7);

    __syncwarp();
    if ((tid & 31) == 0) mbar_arrive_(eb);          // 16 warp-arrivals free slot

    // rotating producer: refill slot s with quarter g+NSLOT
    if (tid == ((g & 15) << 5)) {
        int gn = g + NSLOT;
        if (gn < NQ_TOTAL) {
            mbar_wait_(eb, (uint32_t)((g / NSLOT) & 1));  // all warps released s
            mbar_expect_tx_(fb, QBYTES);
            bulk_g2s_(smem_u32(ws), quarter_addr(wp, gn), QBYTES, fb);
        }
    }
}

__device__ __forceinline__ float4 reduce8(const float4 (&p)[8][2][64], int row, int q) {
    float4 s  = f4add(p[0][row][q], p[1][row][q]);
    float4 s2 = f4add(p[2][row][q], p[3][row][q]);
    float4 s3 = f4add(p[4][row][q], p[5][row][q]);
    float4 s4 = f4add(p[6][row][q], p[7][row][q]);
    return f4add(f4add(s, s2), f4add(s3, s4));
}

__device__ __forceinline__ void cell(
    const float (*in)[H_], float (*h)[H_],
    float (*n0s)[H_], float (*n1s)[H_],
    float4 (&part)[8][2][64], float (*bs)[H_],
    uint64_t* fullb, uint64_t* emptyb, const WPtrs& wp,
    int g0, const float* __restrict__ bias_g,
    int tid, int q, int kc,
    float* __restrict__ o0, float* __restrict__ o1)
{
    // prefetch the 3x256 biases for this cell into smem (completes during node0)
    if (tid < 192) {
        cpasync16_(smem_u32(&bs[0][0]) + tid * 16, bias_g + tid * 4);
        cpasync_commit_();
    }

    const int rrow = tid >> 6;       // reducer row (tid<128)
    const int rq = tid & 63;
    float4 v0 = {0.f, 0.f, 0.f, 0.f};
    float4 u  = {0.f, 0.f, 0.f, 0.f};

    // ---------- node 0: tanh(x@Wi + h@Wh[0] + b[0]) : 8 phases ----------
    {
        float4 a0 = {0.f,0.f,0.f,0.f}, a1 = {0.f,0.f,0.f,0.f};
        #pragma unroll
        for (int ph = 0; ph < 8; ++ph) {
            const float (*act)[H_] = (ph < 4) ? in : (const float (*)[H_])h;
            consume_phase(g0 + ph, ph & 3, act, a0, a1, fullb, emptyb, wp, tid, q, kc);
        }
        part[kc][0][q] = a0; part[kc][1][q] = a1;
    }
    if (tid < 192) cpasync_wait0_();   // bias (and any x-prefetch) landed
    __syncthreads();
    if (tid < 128) {
        float4 s = reduce8(part, rrow, rq);
        float4 bv = *reinterpret_cast<const float4*>(&bs[0][4 * rq]);
        v0.x = tanhf(s.x + bv.x); v0.y = tanhf(s.y + bv.y);
        v0.z = tanhf(s.z + bv.z); v0.w = tanhf(s.w + bv.w);
        *reinterpret_cast<float4*>(&n0s[rrow][4 * rq]) = v0;
    }
    __syncthreads();

    // ---------- node 1: relu(n0@Wh[1] + b[1]) + n0 : 4 phases ----------
    {
        float4 a0 = {0.f,0.f,0.f,0.f}, a1 = {0.f,0.f,0.f,0.f};
        #pragma unroll
        for (int ph = 0; ph < 4; ++ph)
            consume_phase(g0 + 8 + ph, ph, (const float (*)[H_])n0s,
                          a0, a1, fullb, emptyb, wp, tid, q, kc);
        part[kc][0][q] = a0; part[kc][1][q] = a1;
    }
    __syncthreads();
    if (tid < 128) {
        float4 s = reduce8(part, rrow, rq);
        float4 bv = *reinterpret_cast<const float4*>(&bs[1][4 * rq]);
        u.x = fmaxf(s.x + bv.x, 0.f) + v0.x;
        u.y = fmaxf(s.y + bv.y, 0.f) + v0.y;
        u.z = fmaxf(s.z + bv.z, 0.f) + v0.z;
        u.w = fmaxf(s.w + bv.w, 0.f) + v0.w;
        *reinterpret_cast<float4*>(&n1s[rrow][4 * rq]) = u;
    }
    __syncthreads();

    // ---------- node 2: sigmoid(n1@Wh[2] + b[2]) + n0 ; h = 0.5*(n1+n2) ----------
    {
        float4 a0 = {0.f,0.f,0.f,0.f}, a1 = {0.f,0.f,0.f,0.f};
        #pragma unroll
        for (int ph = 0; ph < 4; ++ph)
            consume_phase(g0 + 12 + ph, ph, (const float (*)[H_])n1s,
                          a0, a1, fullb, emptyb, wp, tid, q, kc);
        part[kc][0][q] = a0; part[kc][1][q] = a1;
    }
    __syncthreads();
    if (tid < 128) {
        float4 s = reduce8(part, rrow, rq);
        float4 bv = *reinterpret_cast<const float4*>(&bs[2][4 * rq]);
        float4 g;
        g.x = 1.f / (1.f + expf(-(s.x + bv.x))) + v0.x;
        g.y = 1.f / (1.f + expf(-(s.y + bv.y))) + v0.y;
        g.z = 1.f / (1.f + expf(-(s.z + bv.z))) + v0.z;
        g.w = 1.f / (1.f + expf(-(s.w + bv.w))) + v0.w;
        float4 hn = make_float4(0.5f * (u.x + g.x), 0.5f * (u.y + g.y),
                                0.5f * (u.z + g.z), 0.5f * (u.w + g.w));
        *reinterpret_cast<float4*>(&h[rrow][4 * rq]) = hn;  // h last read in node 0
        if (o0) {
            float* op = rrow ? o1 : o0;
            *reinterpret_cast<float4*>(op + 4 * rq) = hn;
        }
    }
    __syncthreads();
}

__global__ void __launch_bounds__(NT, 1)
rnn_pipe_kernel(const float* __restrict__ x,       // [B,T,D]
                const float* __restrict__ hidden,  // [L,B,H]
                const float* __restrict__ Win0,    // [T,D,H]
                const float* __restrict__ Wh0,     // [T,3,H,H]
                const float* __restrict__ b0,      // [T,3,H]
                const float* __restrict__ Win1,    // [T,H,H]
                const float* __restrict__ Wh1,     // [T,3,H,H]
                const float* __restrict__ b1,      // [T,3,H]
                float* __restrict__ out,           // [B,T,H]
                float* __restrict__ hout)          // [L,B,H]
{
    __shared__ __align__(16) float xs[2][H_];
    __shared__ __align__(16) float h0s[2][H_];
    __shared__ __align__(16) float h1s[2][H_];
    __shared__ __align__(16) float n0s[2][H_];
    __shared__ __align__(16) float n1s[2][H_];
    __shared__ __align__(16) float bs[3][H_];
    __shared__ __align__(16) float4 part[8][2][64];
    __shared__ __align__(8) uint64_t fullb[NSLOT];
    __shared__ __align__(8) uint64_t emptyb[NSLOT];

    const int tid = threadIdx.x;
    const int q = tid & 63;
    const int kc = tid >> 6;
    const int r0 = blockIdx.x * 2;

    WPtrs wp{Win0, Wh0, Win1, Wh1};

    if (tid == 0) {
        #pragma unroll
        for (int s = 0; s < NSLOT; ++s) {
            mbar_init_(smem_u32(&fullb[s]), 1);     // producer expect_tx arrive
            mbar_init_(smem_u32(&emptyb[s]), 16);   // one arrive per warp
        }
    }

    // initial hidden + x(t=0)
    for (int i = tid; i < 2 * H_; i += NT) {
        int row = i >> 8, j = i & 255;
        h0s[row][j] = hidden[(r0 + row) * H_ + j];
        h1s[row][j] = hidden[(B_ + r0 + row) * H_ + j];
        xs[row][j] = x[((size_t)(r0 + row) * T_) * D_ + j];
    }
    __syncthreads();

    // prefill ring
    if (tid == 0) {
        #pragma unroll
        for (int g = 0; g < NSLOT; ++g) {
            mbar_expect_tx_(smem_u32(&fullb[g]), QBYTES);
            bulk_g2s_(smem_u32(ring + g * QFLOATS), quarter_addr(wp, g),
                      QBYTES, smem_u32(&fullb[g]));
        }
    }

    for (int t = 0; t < T_; ++t) {
        int g0 = (2 * t) * 16;

        cell(xs, h0s, n0s, n1s, part, bs, fullb, emptyb, wp,
             g0, b0 + (size_t)t * 3 * H_, tid, q, kc, nullptr, nullptr);

        // prefetch x[t+1] into xs (xs fully consumed by layer-0 node 0);
        // issuers (tid<64) hit cp.async.wait_group 0 inside the next cell's
        // bias wait, and the pre-reduce __syncthreads publishes it.
        if (t + 1 < T_ && tid < 64) {
            #pragma unroll
            for (int c = 0; c < 2; ++c) {
                int i = tid + 64 * c;              // 16B chunk index, 0..127
                int row = (i * 4) >> 8, col = (i * 4) & 255;
                cpasync16_(smem_u32(&xs[0][0]) + i * 16,
                           x + ((size_t)(r0 + row) * T_ + (t + 1)) * D_ + col);
            }
            cpasync_commit_();
        }

        cell(h0s, h1s, n0s, n1s, part, bs, fullb, emptyb, wp,
             g0 + 16, b1 + (size_t)t * 3 * H_, tid, q, kc,
             out + ((size_t)r0 * T_ + t) * H_,
             out + ((size_t)(r0 + 1) * T_ + t) * H_);
    }

    for (int i = tid; i < 2 * H_; i += NT) {
        int row = i >> 8, j = i & 255;
        hout[(r0 + row) * H_ + j] = h0s[row][j];
        hout[(B_ + r0 + row) * H_ + j] = h1s[row][j];
    }
}

extern "C" void kernel_launch(void* const* d_in, const int* in_sizes, int n_in,
                              void* d_out, int out_size) {
    const float* x      = (const float*)d_in[0];
    const float* hidden = (const float*)d_in[1];
    const float* Win0   = (const float*)d_in[2];
    const float* Wh0    = (const float*)d_in[3];
    const float* b0     = (const float*)d_in[4];
    const float* Win1   = (const float*)d_in[5];
    const float* Wh1    = (const float*)d_in[6];
    const float* b1     = (const float*)d_in[7];

    float* out  = (float*)d_out;                  // [B,T,H]
    float* hout = out + (size_t)B_ * T_ * H_;     // [L,B,H]

    cudaFuncSetAttribute(rnn_pipe_kernel,
                         cudaFuncAttributeMaxDynamicSharedMemorySize,
                         NSLOT * QBYTES);

    rnn_pipe_kernel<<<B_ / 2, NT, NSLOT * QBYTES>>>(
        x, hidden, Win0, Wh0, b0, Win1, Wh1, b1, out, hout);
}

// round 7
// speedup vs baseline: 1.3833x; 1.3833x over previous
#include <cuda_runtime.h>
#include <cstdint>

#define B_ 128
#define T_ 64
#define D_ 256
#define H_ 256
#define NT 512
#define NPAIR 64     // batch row-pairs

// Layer-pipelined persistent RNN:
//   64 producer CTAs (layer 0) + 64 consumer CTAs (layer 1), 128 CTAs total,
//   all co-resident (one wave on 148 SMs). Producer b computes layer-0 cells
//   for batch rows 2b,2b+1 over all T and publishes h0(t) to a __device__
//   scratch buffer with a per-pair release flag. Consumer b trails one step,
//   acquiring h0(t) and computing layer 1 + the kernel outputs. Each CTA runs
//   64 cells instead of 128 -> ~2x concurrency on the serial chain.
// Compute core = R4 layout: thread (q=tid&63 -> 4 output cols, kc=tid>>6 ->
// 32-row k-chunk) accumulates float4 partials for both rows with LDG.128
// weight loads; 128 reducer threads fold 8 partials + bias + activation.

__device__ float g_h0buf[NPAIR][T_][2][H_];   // 8 MB handoff buffer
__device__ int   g_flags[NPAIR * 32];         // one flag per pair, 128B apart

__device__ __forceinline__ void f4fma(float4& a, float s, const float4 w) {
    a.x = fmaf(s, w.x, a.x); a.y = fmaf(s, w.y, a.y);
    a.z = fmaf(s, w.z, a.z); a.w = fmaf(s, w.w, a.w);
}
__device__ __forceinline__ float4 f4add(float4 a, float4 b) {
    return make_float4(a.x + b.x, a.y + b.y, a.z + b.z, a.w + b.w);
}

__device__ __forceinline__ void mv_partial(
    const float* __restrict__ W,          // [256,256] row-major
    const float* __restrict__ a0,         // smem row 0 [256]
    const float* __restrict__ a1,         // smem row 1 [256]
    float4& acc0, float4& acc1, int q, int kc)
{
    const float4* __restrict__ w4 =
        reinterpret_cast<const float4*>(W) + (size_t)(kc * 32) * (H_ / 4) + q;
    const float4* __restrict__ av0 = reinterpret_cast<const float4*>(a0) + kc * 8;
    const float4* __restrict__ av1 = reinterpret_cast<const float4*>(a1) + kc * 8;
    #pragma unroll
    for (int g = 0; g < 4; ++g) {
        float4 w[8];
        #pragma unroll
        for (int k = 0; k < 8; ++k) w[k] = w4[(g * 8 + k) * (H_ / 4)];
        float4 A0a = av0[g * 2], A0b = av0[g * 2 + 1];
        float4 A1a = av1[g * 2], A1b = av1[g * 2 + 1];
        f4fma(acc0, A0a.x, w[0]); f4fma(acc1, A1a.x, w[0]);
        f4fma(acc0, A0a.y, w[1]); f4fma(acc1, A1a.y, w[1]);
        f4fma(acc0, A0a.z, w[2]); f4fma(acc1, A1a.z, w[2]);
        f4fma(acc0, A0a.w, w[3]); f4fma(acc1, A1a.w, w[3]);
        f4fma(acc0, A0b.x, w[4]); f4fma(acc1, A1b.x, w[4]);
        f4fma(acc0, A0b.y, w[5]); f4fma(acc1, A1b.y, w[5]);
        f4fma(acc0, A0b.z, w[6]); f4fma(acc1, A1b.z, w[6]);
        f4fma(acc0, A0b.w, w[7]); f4fma(acc1, A1b.w, w[7]);
    }
}

__device__ __forceinline__ float4 reduce8(const float4 (&p)[8][2][64], int row, int q) {
    float4 s  = f4add(p[0][row][q], p[1][row][q]);
    float4 s2 = f4add(p[2][row][q], p[3][row][q]);
    float4 s3 = f4add(p[4][row][q], p[5][row][q]);
    float4 s4 = f4add(p[6][row][q], p[7][row][q]);
    return f4add(f4add(s, s2), f4add(s3, s4));
}

__device__ __forceinline__ void cell(
    const float (&in)[2][H_], float (&h)[2][H_],
    float (&n0s)[2][H_], float (&n1s)[2][H_],
    float4 (&part)[8][2][64],
    const float* __restrict__ Wi, const float* __restrict__ Wh,
    const float* __restrict__ bias,
    int tid, int q, int kc,
    float* __restrict__ o0, float* __restrict__ o1)
{
    // ---------- node 0 ----------
    {
        float4 a0 = {0.f,0.f,0.f,0.f}, a1 = {0.f,0.f,0.f,0.f};
        mv_partial(Wi, in[0], in[1], a0, a1, q, kc);
        mv_partial(Wh, h[0], h[1], a0, a1, q, kc);
        part[kc][0][q] = a0; part[kc][1][q] = a1;
    }
    __syncthreads();
    float4 v0 = {0.f,0.f,0.f,0.f};
    float4 u  = {0.f,0.f,0.f,0.f};
    if (tid < 128) {
        const int row = tid >> 6;
        float4 s = reduce8(part, row, q);
        float4 bv = *reinterpret_cast<const float4*>(bias + 4 * q);
        v0.x = tanhf(s.x + bv.x); v0.y = tanhf(s.y + bv.y);
        v0.z = tanhf(s.z + bv.z); v0.w = tanhf(s.w + bv.w);
        *reinterpret_cast<float4*>(&n0s[row][4 * q]) = v0;
    }
    __syncthreads();

    // ---------- node 1 ----------
    {
        float4 a0 = {0.f,0.f,0.f,0.f}, a1 = {0.f,0.f,0.f,0.f};
        mv_partial(Wh + (size_t)H_ * H_, n0s[0], n0s[1], a0, a1, q, kc);
        part[kc][0][q] = a0; part[kc][1][q] = a1;
    }
    __syncthreads();
    if (tid < 128) {
        const int row = tid >> 6;
        float4 s = reduce8(part, row, q);
        float4 bv = *reinterpret_cast<const float4*>(bias + H_ + 4 * q);
        u.x = fmaxf(s.x + bv.x, 0.f) + v0.x;
        u.y = fmaxf(s.y + bv.y, 0.f) + v0.y;
        u.z = fmaxf(s.z + bv.z, 0.f) + v0.z;
        u.w = fmaxf(s.w + bv.w, 0.f) + v0.w;
        *reinterpret_cast<float4*>(&n1s[row][4 * q]) = u;
    }
    __syncthreads();

    // ---------- node 2 ----------
    {
        float4 a0 = {0.f,0.f,0.f,0.f}, a1 = {0.f,0.f,0.f,0.f};
        mv_partial(Wh + 2 * (size_t)H_ * H_, n1s[0], n1s[1], a0, a1, q, kc);
        part[kc][0][q] = a0; part[kc][1][q] = a1;
    }
    __syncthreads();
    if (tid < 128) {
        const int row = tid >> 6;
        float4 s = reduce8(part, row, q);
        float4 bv = *reinterpret_cast<const float4*>(bias + 2 * H_ + 4 * q);
        float4 g;
        g.x = 1.f / (1.f + expf(-(s.x + bv.x))) + v0.x;
        g.y = 1.f / (1.f + expf(-(s.y + bv.y))) + v0.y;
        g.z = 1.f / (1.f + expf(-(s.z + bv.z))) + v0.z;
        g.w = 1.f / (1.f + expf(-(s.w + bv.w))) + v0.w;
        float4 hn = make_float4(0.5f * (u.x + g.x), 0.5f * (u.y + g.y),
                                0.5f * (u.z + g.z), 0.5f * (u.w + g.w));
        *reinterpret_cast<float4*>(&h[row][4 * q]) = hn;
        if (o0) {
            float* op = row ? o1 : o0;
            *reinterpret_cast<float4*>(op + 4 * q) = hn;
        }
    }
    __syncthreads();
}

__global__ void reset_flags_kernel() {
    g_flags[threadIdx.x * 32] = 0;
}

__global__ void __launch_bounds__(NT, 1)
rnn_pipeline_kernel(const float* __restrict__ x,       // [B,T,D]
                    const float* __restrict__ hidden,  // [L,B,H]
                    const float* __restrict__ Win0,    // [T,D,H]
                    const float* __restrict__ Wh0,     // [T,3,H,H]
                    const float* __restrict__ b0,      // [T,3,H]
                    const float* __restrict__ Win1,    // [T,H,H]
                    const float* __restrict__ Wh1,     // [T,3,H,H]
                    const float* __restrict__ b1,      // [T,3,H]
                    float* __restrict__ out,           // [B,T,H]
                    float* __restrict__ hout)          // [L,B,H]
{
    __shared__ __align__(16) float xs[2][H_];
    __shared__ __align__(16) float hs[2][H_];
    __shared__ __align__(16) float n0s[2][H_];
    __shared__ __align__(16) float n1s[2][H_];
    __shared__ __align__(16) float4 part[8][2][64];

    const int tid = threadIdx.x;
    const int q = tid & 63;
    const int kc = tid >> 6;
    const int pair = blockIdx.x >> 1;       // 0..63
    const int layer = blockIdx.x & 1;       // 0: producer, 1: consumer
    const int r0 = pair * 2;
    const int row = tid >> 8, j = tid & 255;   // for 512-wide row copies

    // initial hidden state for this CTA's layer
    hs[row][j] = hidden[((size_t)layer * B_ + r0 + row) * H_ + j];
    __syncthreads();

    if (layer == 0) {
        // ---------------- producer: layer 0 ----------------
        for (int t = 0; t < T_; ++t) {
            xs[row][j] = x[((size_t)(r0 + row) * T_ + t) * D_ + j];
            __syncthreads();

            cell(xs, hs, n0s, n1s, part,
                 Win0 + (size_t)t * D_ * H_,
                 Wh0 + (size_t)t * 3 * H_ * H_,
                 b0 + (size_t)t * 3 * H_,
                 tid, q, kc, nullptr, nullptr);

            // publish h0(t): stores -> per-thread fence -> barrier -> release
            __stcg(&g_h0buf[pair][t][row][j], hs[row][j]);
            __threadfence();
            __syncthreads();
            if (tid == 0)
                asm volatile("st.release.gpu.global.s32 [%0], %1;"
                             :: "l"(&g_flags[pair * 32]), "r"(t + 1) : "memory");
        }
        hout[(r0 + row) * H_ + j] = hs[row][j];
    } else {
        // ---------------- consumer: layer 1 ----------------
        for (int t = 0; t < T_; ++t) {
            if (tid == 0) {
                int v;
                do {
                    asm volatile("ld.acquire.gpu.global.s32 %0, [%1];"
                                 : "=r"(v) : "l"(&g_flags[pair * 32]) : "memory");
                    if (v < t + 1) __nanosleep(128);
                } while (v < t + 1);
            }
            __syncthreads();
            xs[row][j] = __ldcg(&g_h0buf[pair][t][row][j]);
            __syncthreads();

            cell(xs, hs, n0s, n1s, part,
                 Win1 + (size_t)t * H_ * H_,
                 Wh1 + (size_t)t * 3 * H_ * H_,
                 b1 + (size_t)t * 3 * H_,
                 tid, q, kc,
                 out + ((size_t)r0 * T_ + t) * H_,
                 out + ((size_t)(r0 + 1) * T_ + t) * H_);
        }
        hout[((size_t)B_ + r0 + row) * H_ + j] = hs[row][j];
    }
}

extern "C" void kernel_launch(void* const* d_in, const int* in_sizes, int n_in,
                              void* d_out, int out_size) {
    const float* x      = (const float*)d_in[0];
    const float* hidden = (const float*)d_in[1];
    const float* Win0   = (const float*)d_in[2];
    const float* Wh0    = (const float*)d_in[3];
    const float* b0     = (const float*)d_in[4];
    const float* Win1   = (const float*)d_in[5];
    const float* Wh1    = (const float*)d_in[6];
    const float* b1     = (const float*)d_in[7];

    float* out  = (float*)d_out;                  // [B,T,H]
    float* hout = out + (size_t)B_ * T_ * H_;     // [L,B,H]

    reset_flags_kernel<<<1, NPAIR>>>();
    rnn_pipeline_kernel<<<2 * NPAIR, NT>>>(x, hidden, Win0, Wh0, b0,
                                           Win1, Wh1, b1, out, hout);
}

// round 8
// speedup vs baseline: 2.1637x; 1.5641x over previous
#include <cuda_runtime.h>
#include <cstdint>

#define B_ 128
#define T_ 64
#define D_ 256
#define H_ 256
#define NT 512
#define NPAIR 64
#define HH (H_ * H_)

// Layer-pipelined persistent RNN (R7 structure) + cross-barrier register
// prefetch of weights. 64 producer CTAs (layer 0) + 64 consumer CTAs
// (layer 1); producer b publishes h0(t) to g_h0buf with a release flag.
// Each matrix stage: thread (q=tid&63 -> 4 cols, kc=tid>>6 -> 32 k-rows)
// holds next stage's k-rows 0-7 in registers (prefetched during the
// previous stage) so post-barrier FMAs start immediately; rows 8-31 are
// streamed through two 4xfloat4 ping-pong buffers. Biases are double-
// buffered in smem one cell ahead; producer prefetches x(t+1) during the
// node-0 reduce window.

__device__ float g_h0buf[NPAIR][T_][2][H_];   // 8 MB handoff buffer
__device__ int   g_flags[NPAIR * 32];

__device__ __forceinline__ void f4fma(float4& a, float s, const float4 w) {
    a.x = fmaf(s, w.x, a.x); a.y = fmaf(s, w.y, a.y);
    a.z = fmaf(s, w.z, a.z); a.w = fmaf(s, w.w, a.w);
}
__device__ __forceinline__ float4 f4add(float4 a, float4 b) {
    return make_float4(a.x + b.x, a.y + b.y, a.z + b.z, a.w + b.w);
}
// group g = 4 consecutive k-rows; w[k] = row (4g+k)'s 4 output cols
__device__ __forceinline__ void load_group(float4 (&w)[4], const float4* w4, int g) {
    #pragma unroll
    for (int k = 0; k < 4; ++k) w[k] = w4[(size_t)(g * 4 + k) * (H_ / 4)];
}
__device__ __forceinline__ void fma_group(const float4 (&w)[4], float4 A0, float4 A1,
                                          float4& acc0, float4& acc1) {
    f4fma(acc0, A0.x, w[0]); f4fma(acc1, A1.x, w[0]);
    f4fma(acc0, A0.y, w[1]); f4fma(acc1, A1.y, w[1]);
    f4fma(acc0, A0.z, w[2]); f4fma(acc1, A1.z, w[2]);
    f4fma(acc0, A0.w, w[3]); f4fma(acc1, A1.w, w[3]);
}

// One 256-k matrix stage. wp/w1 hold THIS stage's k-rows 0-7 on entry and
// are refilled with NEXT stage's (Wn's) k-rows 0-7 during execution.
__device__ __forceinline__ void stage_core(
    const float* __restrict__ W, const float* __restrict__ Wn,
    float4 (&wp)[4], float4 (&w1)[4],
    const float* __restrict__ a0r, const float* __restrict__ a1r,
    float4& acc0, float4& acc1, int q, int kc)
{
    const float4* w4  = reinterpret_cast<const float4*>(W)  + (size_t)(kc * 32) * (H_ / 4) + q;
    const float4* wn4 = reinterpret_cast<const float4*>(Wn) + (size_t)(kc * 32) * (H_ / 4) + q;
    const float4* av0 = reinterpret_cast<const float4*>(a0r) + kc * 8;
    const float4* av1 = reinterpret_cast<const float4*>(a1r) + kc * 8;
    float4 wa[4], wb[4];
    load_group(wa, w4, 2);                              // rows 8-11
    load_group(wb, w4, 3);                              // rows 12-15
    fma_group(wp, av0[0], av1[0], acc0, acc1);          // rows 0-3 (prefetched)
    load_group(wp, wn4, 0);                             // prefetch next stage rows 0-3
    fma_group(w1, av0[1], av1[1], acc0, acc1);          // rows 4-7 (prefetched)
    load_group(w1, wn4, 1);                             // prefetch next stage rows 4-7
    fma_group(wa, av0[2], av1[2], acc0, acc1); load_group(wa, w4, 4);
    fma_group(wb, av0[3], av1[3], acc0, acc1); load_group(wb, w4, 5);
    fma_group(wa, av0[4], av1[4], acc0, acc1); load_group(wa, w4, 6);
    fma_group(wb, av0[5], av1[5], acc0, acc1); load_group(wb, w4, 7);
    fma_group(wa, av0[6], av1[6], acc0, acc1);
    fma_group(wb, av0[7], av1[7], acc0, acc1);
}

__device__ __forceinline__ float4 reduce8(const float4 (&p)[8][2][64], int row, int q) {
    float4 s  = f4add(p[0][row][q], p[1][row][q]);
    float4 s2 = f4add(p[2][row][q], p[3][row][q]);
    float4 s3 = f4add(p[4][row][q], p[5][row][q]);
    float4 s4 = f4add(p[6][row][q], p[7][row][q]);
    return f4add(f4add(s, s2), f4add(s3, s4));
}

__global__ void reset_flags_kernel() {
    g_flags[threadIdx.x * 32] = 0;
}

__global__ void __launch_bounds__(NT, 1)
rnn_pf_kernel(const float* __restrict__ x,       // [B,T,D]
              const float* __restrict__ hidden,  // [L,B,H]
              const float* __restrict__ Win0,    // [T,D,H]
              const float* __restrict__ Wh0,     // [T,3,H,H]
              const float* __restrict__ b0,      // [T,3,H]
              const float* __restrict__ Win1,    // [T,H,H]
              const float* __restrict__ Wh1,     // [T,3,H,H]
              const float* __restrict__ b1,      // [T,3,H]
              float* __restrict__ out,           // [B,T,H]
              float* __restrict__ hout)          // [L,B,H]
{
    __shared__ __align__(16) float xs[2][H_];
    __shared__ __align__(16) float hs[2][H_];
    __shared__ __align__(16) float n0s[2][H_];
    __shared__ __align__(16) float n1s[2][H_];
    __shared__ __align__(16) float bs[2][3][H_];     // double-buffered biases
    __shared__ __align__(16) float4 part[8][2][64];

    const int tid = threadIdx.x;
    const int q = tid & 63;
    const int kc = tid >> 6;
    const int pair = blockIdx.x >> 1;
    const int layer = blockIdx.x & 1;
    const int r0 = pair * 2;
    const int row = tid >> 8, j = tid & 255;

    const float* Wi_base   = layer ? Win1 : Win0;
    const float* Wh_base   = layer ? Wh1 : Wh0;
    const float* bias_base = layer ? b1 : b0;

    hs[row][j] = hidden[((size_t)layer * B_ + r0 + row) * H_ + j];
    if (layer == 0)
        xs[row][j] = x[((size_t)(r0 + row) * T_) * D_ + j];
    if (tid < 192)     // bias(t=0) into bs[0]
        *reinterpret_cast<float4*>(&bs[0][0][0] + tid * 4) =
            *reinterpret_cast<const float4*>(bias_base + tid * 4);
    __syncthreads();

    // bootstrap prefetch window with stage A(t=0) rows 0-7
    float4 wp[4], w1[4];
    {
        const float4* w4 = reinterpret_cast<const float4*>(Wi_base)
                         + (size_t)(kc * 32) * (H_ / 4) + q;
        load_group(wp, w4, 0);
        load_group(w1, w4, 1);
    }

    for (int t = 0; t < T_; ++t) {
        const float* WiT = Wi_base + (size_t)t * (D_ * H_);
        const float* WhT = Wh_base + (size_t)t * 3 * HH;
        const int tn = (t + 1 < T_) ? t + 1 : 0;
        const float* WiN = Wi_base + (size_t)tn * (D_ * H_);
        const float* bsc = &bs[t & 1][0][0];

        const float* a0A;        // stage-A activation rows
        const float* a1A;
        if (layer == 0) {
            a0A = xs[0]; a1A = xs[1];
        } else {
            // acquire h0(t), then read it straight from gmem in stage A
            if (tid == 0) {
                int v;
                do {
                    asm volatile("ld.acquire.gpu.global.s32 %0, [%1];"
                                 : "=r"(v) : "l"(&g_flags[pair * 32]) : "memory");
                    if (v < t + 1) __nanosleep(64);
                } while (v < t + 1);
            }
            __syncthreads();
            a0A = &g_h0buf[pair][t][0][0];
            a1A = &g_h0buf[pair][t][1][0];
        }

        float4 v0 = {0.f,0.f,0.f,0.f};
        float4 u  = {0.f,0.f,0.f,0.f};

        // ---------- node 0: tanh(x@Wi + h@Wh[0] + b[0]) ----------
        {
            float4 acc0 = {0.f,0.f,0.f,0.f}, acc1 = {0.f,0.f,0.f,0.f};
            stage_core(WiT, WhT, wp, w1, a0A, a1A, acc0, acc1, q, kc);
            stage_core(WhT, WhT + HH, wp, w1, hs[0], hs[1], acc0, acc1, q, kc);
            part[kc][0][q] = acc0; part[kc][1][q] = acc1;
        }
        __syncthreads();
        if (tid < 128) {
            const int rrow = tid >> 6;
            float4 s = reduce8(part, rrow, q);
            float4 bv = *reinterpret_cast<const float4*>(bsc + 4 * q);
            v0.x = tanhf(s.x + bv.x); v0.y = tanhf(s.y + bv.y);
            v0.z = tanhf(s.z + bv.z); v0.w = tanhf(s.w + bv.w);
            *reinterpret_cast<float4*>(&n0s[rrow][4 * q]) = v0;
        } else if (tid < 320) {
            // prefetch bias(t+1) into the other slab
            int i = tid - 128;   // 0..191
            *reinterpret_cast<float4*>(&bs[(t + 1) & 1][0][0] + i * 4) =
                *reinterpret_cast<const float4*>(bias_base + (size_t)tn * 3 * H_ + i * 4);
        } else if (tid >= 384 && layer == 0 && t + 1 < T_) {
            // producer: prefetch x(t+1) into xs (stage-A reads finished pre-barrier)
            int i = tid - 384;              // 0..127
            int rr = i >> 6, col = (i & 63) * 4;
            *reinterpret_cast<float4*>(&xs[rr][col]) =
                *reinterpret_cast<const float4*>(
                    &x[((size_t)(r0 + rr) * T_ + t + 1) * D_ + col]);
        }
        __syncthreads();

        // ---------- node 1: relu(n0@Wh[1] + b[1]) + n0 ----------
        {
            float4 acc0 = {0.f,0.f,0.f,0.f}, acc1 = {0.f,0.f,0.f,0.f};
            stage_core(WhT + HH, WhT + 2 * HH, wp, w1, n0s[0], n0s[1],
                       acc0, acc1, q, kc);
            part[kc][0][q] = acc0; part[kc][1][q] = acc1;
        }
        __syncthreads();
        if (tid < 128) {
            const int rrow = tid >> 6;
            float4 s = reduce8(part, rrow, q);
            float4 bv = *reinterpret_cast<const float4*>(bsc + H_ + 4 * q);
            u.x = fmaxf(s.x + bv.x, 0.f) + v0.x;
            u.y = fmaxf(s.y + bv.y, 0.f) + v0.y;
            u.z = fmaxf(s.z + bv.z, 0.f) + v0.z;
            u.w = fmaxf(s.w + bv.w, 0.f) + v0.w;
            *reinterpret_cast<float4*>(&n1s[rrow][4 * q]) = u;
        }
        __syncthreads();

        // ---------- node 2: sigmoid(n1@Wh[2] + b[2]) + n0 ; h = 0.5*(n1+n2) ----------
        {
            float4 acc0 = {0.f,0.f,0.f,0.f}, acc1 = {0.f,0.f,0.f,0.f};
            stage_core(WhT + 2 * HH, WiN, wp, w1, n1s[0], n1s[1],
                       acc0, acc1, q, kc);
            part[kc][0][q] = acc0; part[kc][1][q] = acc1;
        }
        __syncthreads();
        if (tid < 128) {
            const int rrow = tid >> 6;
            float4 s = reduce8(part, rrow, q);
            float4 bv = *reinterpret_cast<const float4*>(bsc + 2 * H_ + 4 * q);
            float4 g;
            g.x = 1.f / (1.f + expf(-(s.x + bv.x))) + v0.x;
            g.y = 1.f / (1.f + expf(-(s.y + bv.y))) + v0.y;
            g.z = 1.f / (1.f + expf(-(s.z + bv.z))) + v0.z;
            g.w = 1.f / (1.f + expf(-(s.w + bv.w))) + v0.w;
            float4 hn = make_float4(0.5f * (u.x + g.x), 0.5f * (u.y + g.y),
                                    0.5f * (u.z + g.z), 0.5f * (u.w + g.w));
            *reinterpret_cast<float4*>(&hs[rrow][4 * q]) = hn;
            if (layer == 0) {
                *reinterpret_cast<float4*>(&g_h0buf[pair][t][rrow][4 * q]) = hn;
                __threadfence();          // storing thread fences its own stores
            } else {
                float* op = out + ((size_t)(r0 + rrow) * T_ + t) * H_;
                *reinterpret_cast<float4*>(op + 4 * q) = hn;
            }
        }
        __syncthreads();
        if (layer == 0 && tid == 0)
            asm volatile("st.release.gpu.global.s32 [%0], %1;"
                         :: "l"(&g_flags[pair * 32]), "r"(t + 1) : "memory");
    }

    hout[((size_t)layer * B_ + r0 + row) * H_ + j] = hs[row][j];
}

extern "C" void kernel_launch(void* const* d_in, const int* in_sizes, int n_in,
                              void* d_out, int out_size) {
    const float* x      = (const float*)d_in[0];
    const float* hidden = (const float*)d_in[1];
    const float* Win0   = (const float*)d_in[2];
    const float* Wh0    = (const float*)d_in[3];
    const float* b0     = (const float*)d_in[4];
    const float* Win1   = (const float*)d_in[5];
    const float* Wh1    = (const float*)d_in[6];
    const float* b1     = (const float*)d_in[7];

    float* out  = (float*)d_out;                  // [B,T,H]
    float* hout = out + (size_t)B_ * T_ * H_;     // [L,B,H]

    reset_flags_kernel<<<1, NPAIR>>>();
    rnn_pf_kernel<<<2 * NPAIR, NT>>>(x, hidden, Win0, Wh0, b0,
                                     Win1, Wh1, b1, out, hout);
}